// round 2
// baseline (speedup 1.0000x reference)
#include <cuda_runtime.h>

#define BB 2
#define LL 1024
#define DD 64
#define NROWS (BB*LL)
#define SCALE 0.35355339059327373f

// persistent activations (no allocation allowed)
__device__ float g_qvs[NROWS*DD];
__device__ float g_kvs[NROWS*DD];
__device__ float g_attq[NROWS*DD];
__device__ float g_attk[NROWS*DD];
__device__ float g_q1[NROWS*DD];
__device__ float g_q2[NROWS*DD];
__device__ float g_kk[NROWS*DD];
__device__ float g_vv[NROWS*DD];

// ---------------------------------------------------------------------------
// Embed: row-wise MLP  concat(obs,s,f)[7] -> 256 -> 64
// grid 4096 (rows 0..2047 = ctx -> kvs, 2048..4095 = test -> qvs), 256 thr
// ---------------------------------------------------------------------------
__global__ __launch_bounds__(256) void embed_kernel(
    const float* __restrict__ s_ctx, const float* __restrict__ f_ctx,
    const float* __restrict__ s_test, const float* __restrict__ table,
    const float* __restrict__ w1, const float* __restrict__ b1,
    const float* __restrict__ w2, const float* __restrict__ b2)
{
    __shared__ float xs[8];
    __shared__ float h[256];
    __shared__ float part[256];
    int row = blockIdx.x, tid = threadIdx.x;
    int sideq = row >> 11;            // 0: ctx, 1: test
    int r = row & 2047;
    int b = r >> 10, pos = r & 1023;
    if (tid < 7) {
        float v;
        if (sideq == 0) {
            v = (tid < 4) ? table[4 + tid]
              : (tid < 6) ? s_ctx[(b*LL + pos)*2 + tid - 4]
                          : f_ctx[b*LL + pos];
        } else {
            v = (tid < 4) ? table[tid]
              : (tid < 6) ? s_test[(b*LL + pos)*2 + tid - 4]
                          : 0.f;
        }
        xs[tid] = v;
    }
    __syncthreads();
    float acc = b1[tid];
#pragma unroll
    for (int i = 0; i < 7; ++i) acc = fmaf(xs[i], w1[i*256 + tid], acc);
    h[tid] = fmaxf(acc, 0.f);
    __syncthreads();
    int o = tid & 63, half = tid >> 6;
    float p = 0.f;
#pragma unroll 8
    for (int j = half*64; j < half*64 + 64; ++j) p = fmaf(h[j], w2[j*64 + o], p);
    part[tid] = p;
    __syncthreads();
    if (tid < 64) {
        float v = part[tid] + part[tid+64] + part[tid+128] + part[tid+192] + b2[tid];
        float* dst = sideq ? g_qvs : g_kvs;
        dst[(b*LL + pos)*64 + tid] = v;
    }
}

// ---------------------------------------------------------------------------
// Projections for one block: q1 = qvs@Wq, q2 = kvs@Wq, k = kvs@Wk, v = kvs@Wv
// grid (64, 4), 256 thr; each CTA: 32 rows x 64 cols
// ---------------------------------------------------------------------------
__global__ __launch_bounds__(256) void proj_kernel(
    int iblk,
    const float* __restrict__ wq, const float* __restrict__ bq,
    const float* __restrict__ wk, const float* __restrict__ bk,
    const float* __restrict__ wv, const float* __restrict__ bv)
{
    __shared__ float sW[64*64];
    __shared__ float sX[32*64];
    int tid = threadIdx.x;
    int mat = blockIdx.y;
    const float *X, *W, *bias; float* dst;
    if (mat == 0)      { X = g_qvs; W = wq + iblk*4096; bias = bq + iblk*64; dst = g_q1; }
    else if (mat == 1) { X = g_kvs; W = wq + iblk*4096; bias = bq + iblk*64; dst = g_q2; }
    else if (mat == 2) { X = g_kvs; W = wk + iblk*4096; bias = bk + iblk*64; dst = g_kk; }
    else               { X = g_kvs; W = wv + iblk*4096; bias = bv + iblk*64; dst = g_vv; }
    int row0 = blockIdx.x * 32;
    for (int n = tid; n < 4096; n += 256) sW[n] = W[n];
    for (int n = tid; n < 2048; n += 256) sX[n] = X[row0*64 + n];
    __syncthreads();
    int r = tid >> 3, c0 = (tid & 7) * 8;
    float acc[8];
#pragma unroll
    for (int i = 0; i < 8; ++i) acc[i] = bias[c0 + i];
#pragma unroll 16
    for (int k = 0; k < 64; ++k) {
        float a = sX[r*64 + k];
#pragma unroll
        for (int i = 0; i < 8; ++i) acc[i] = fmaf(a, sW[k*64 + c0 + i], acc[i]);
    }
#pragma unroll
    for (int i = 0; i < 8; ++i) dst[(row0 + r)*64 + c0 + i] = acc[i];
}

// ---------------------------------------------------------------------------
// Fused biased attention + out-proj + residual + LN.
// grid (128, B, 2): z=0 q-side, z=1 k-side. CTA = 8 warps = 8 queries.
// warp-per-query; lanes over keys; online softmax; butterfly merge.
// ---------------------------------------------------------------------------
__global__ __launch_bounds__(256) void attn_kernel(
    int iblk,
    const float* __restrict__ s_test, const float* __restrict__ s_ctx,
    const float* __restrict__ bw1, const float* __restrict__ bb1,
    const float* __restrict__ bw2, const float* __restrict__ bb2,
    const float* __restrict__ wo, const float* __restrict__ bo,
    const float* __restrict__ ns, const float* __restrict__ nb)
{
    __shared__ float4 sKf4[1024];   // 64 keys x 16 float4, XOR swizzled
    __shared__ float4 sVf4[1024];
    __shared__ float  sQ[512];      // 8 queries x 64
    __shared__ float  sSk[128];     // 64 keys x 2 coords
    __shared__ float  sW2[128];     // 16 x 8

    const int tid = threadIdx.x, wid = tid >> 5, lane = tid & 31;
    const int side = blockIdx.z, b = blockIdx.y;
    const int q = blockIdx.x * 8 + wid;
    const int qrow = b * LL + q;

    const float* Qp  = side ? g_q2 : g_q1;
    const float* sqc = side ? s_ctx : s_test;

    float w1r[16], b1r[16], b2r[8];
    {
        const float* w1g = bw1 + iblk*16;
        const float* b1g = bb1 + iblk*16;
        const float* b2g = bb2 + iblk*8;
#pragma unroll
        for (int j = 0; j < 16; ++j) { w1r[j] = w1g[j]; b1r[j] = b1g[j]; }
#pragma unroll
        for (int h = 0; h < 8; ++h) b2r[h] = b2g[h];
    }
    if (tid < 128) sW2[tid] = bw2[iblk*128 + tid];
    for (int n = tid; n < 512; n += 256)
        sQ[n] = Qp[(b*LL + blockIdx.x*8)*64 + n];
    const float sqx = sqc[qrow*2], sqy = sqc[qrow*2 + 1];

    float m[8], l[8], o[64];
#pragma unroll
    for (int h = 0; h < 8; ++h) { m[h] = -1e30f; l[h] = 0.f; }
#pragma unroll
    for (int d = 0; d < 64; ++d) o[d] = 0.f;

    const float4* sQf4  = ((const float4*)sQ) + wid*16;
    const float4* sW2f4 = (const float4*)sW2;

    for (int t = 0; t < 16; ++t) {
        __syncthreads();
        const float4* Kg = (const float4*)(g_kk + (b*LL + t*64)*64);
        const float4* Vg = (const float4*)(g_vv + (b*LL + t*64)*64);
        for (int n = tid; n < 1024; n += 256) {
            int kr = n >> 4, c = n & 15;
            int sw = (kr << 4) + (c ^ (kr & 15));
            sKf4[sw] = Kg[n];
            sVf4[sw] = Vg[n];
        }
        if (tid < 128) sSk[tid] = s_ctx[(b*LL + t*64)*2 + tid];
        __syncthreads();

#pragma unroll
        for (int kk = 0; kk < 2; ++kk) {
            const int k  = (kk << 5) + lane;
            const int kb = k << 4, ksw = k & 15;
            float dx = sqx - sSk[2*k], dy = sqy - sSk[2*k + 1];
            float dist = fmaf(dx, dx, dy*dy);

            float bias[8];
#pragma unroll
            for (int h = 0; h < 8; ++h) bias[h] = b2r[h];
#pragma unroll
            for (int j = 0; j < 16; ++j) {
                float rr = fmaxf(fmaf(dist, w1r[j], b1r[j]), 0.f);
                float4 wa = sW2f4[2*j], wb = sW2f4[2*j + 1];
                bias[0] = fmaf(rr, wa.x, bias[0]);
                bias[1] = fmaf(rr, wa.y, bias[1]);
                bias[2] = fmaf(rr, wa.z, bias[2]);
                bias[3] = fmaf(rr, wa.w, bias[3]);
                bias[4] = fmaf(rr, wb.x, bias[4]);
                bias[5] = fmaf(rr, wb.y, bias[5]);
                bias[6] = fmaf(rr, wb.z, bias[6]);
                bias[7] = fmaf(rr, wb.w, bias[7]);
            }

            float dots[8];
#pragma unroll
            for (int h = 0; h < 8; ++h) dots[h] = 0.f;
#pragma unroll
            for (int c = 0; c < 16; ++c) {
                float4 qv = sQf4[c];
                float4 kv = sKf4[kb + (c ^ ksw)];
                int h = c >> 1;
                dots[h] = fmaf(qv.x, kv.x, dots[h]);
                dots[h] = fmaf(qv.y, kv.y, dots[h]);
                dots[h] = fmaf(qv.z, kv.z, dots[h]);
                dots[h] = fmaf(qv.w, kv.w, dots[h]);
            }

#pragma unroll
            for (int h = 0; h < 8; ++h) {
                float s = fmaf(dots[h], SCALE, bias[h]);
                float p;
                if (s > m[h]) {               // rare rescale path
                    float a = __expf(m[h] - s);
                    l[h] *= a;
#pragma unroll
                    for (int d = 0; d < 8; ++d) o[h*8 + d] *= a;
                    m[h] = s;
                    p = 1.f;
                } else {
                    p = __expf(s - m[h]);
                }
                l[h] += p;
                float4 v0 = sVf4[kb + ((2*h) ^ ksw)];
                float4 v1 = sVf4[kb + ((2*h + 1) ^ ksw)];
                o[h*8+0] = fmaf(p, v0.x, o[h*8+0]);
                o[h*8+1] = fmaf(p, v0.y, o[h*8+1]);
                o[h*8+2] = fmaf(p, v0.z, o[h*8+2]);
                o[h*8+3] = fmaf(p, v0.w, o[h*8+3]);
                o[h*8+4] = fmaf(p, v1.x, o[h*8+4]);
                o[h*8+5] = fmaf(p, v1.y, o[h*8+5]);
                o[h*8+6] = fmaf(p, v1.z, o[h*8+6]);
                o[h*8+7] = fmaf(p, v1.w, o[h*8+7]);
            }
        }
    }

    // merge lanes: common max, scale, butterfly sums
#pragma unroll
    for (int h = 0; h < 8; ++h) {
        float M = m[h];
#pragma unroll
        for (int off = 16; off; off >>= 1)
            M = fmaxf(M, __shfl_xor_sync(0xffffffffu, M, off));
        float sc = __expf(m[h] - M);
        float lh = l[h] * sc;
#pragma unroll
        for (int off = 16; off; off >>= 1)
            lh += __shfl_xor_sync(0xffffffffu, lh, off);
#pragma unroll
        for (int d = 0; d < 8; ++d) o[h*8 + d] *= sc;
        l[h] = lh;
    }
#pragma unroll
    for (int d = 0; d < 64; ++d) {
        float v = o[d];
#pragma unroll
        for (int off = 16; off; off >>= 1)
            v += __shfl_xor_sync(0xffffffffu, v, off);
        o[d] = v;
    }
#pragma unroll
    for (int h = 0; h < 8; ++h) {
        float inv = 1.f / l[h];
#pragma unroll
        for (int d = 0; d < 8; ++d) o[h*8 + d] *= inv;
    }

    // epilogue: out-proj (Wo reuses sK smem) + residual + LN
    __syncthreads();
    float* sWo = (float*)sKf4;
    const float* Wog = wo + iblk*4096;
    for (int n = tid; n < 4096; n += 256) sWo[n] = Wog[n];
    __syncthreads();

    const int j0 = lane, j1 = lane + 32;
    float acc0 = bo[iblk*64 + j0], acc1 = bo[iblk*64 + j1];
#pragma unroll
    for (int i = 0; i < 64; ++i) {
        float a = o[i];
        acc0 = fmaf(a, sWo[i*64 + j0], acc0);
        acc1 = fmaf(a, sWo[i*64 + j1], acc1);
    }
    const float* src = side ? g_kvs : g_qvs;
    acc0 += src[qrow*64 + j0];
    acc1 += src[qrow*64 + j1];

    float ssum = acc0 + acc1;
#pragma unroll
    for (int off = 16; off; off >>= 1)
        ssum += __shfl_xor_sync(0xffffffffu, ssum, off);
    float mu = ssum * (1.f/64.f);
    float e0 = acc0 - mu, e1 = acc1 - mu;
    float vv = fmaf(e0, e0, e1*e1);
#pragma unroll
    for (int off = 16; off; off >>= 1)
        vv += __shfl_xor_sync(0xffffffffu, vv, off);
    float rstd = rsqrtf(vv * (1.f/64.f) + 1e-6f);

    float* outp = side ? g_attk : g_attq;
    const float* nsp = ns + iblk*64;
    const float* nbp = nb + iblk*64;
    outp[qrow*64 + j0] = e0 * rstd * nsp[j0] + nbp[j0];
    outp[qrow*64 + j1] = e1 * rstd * nsp[j1] + nbp[j1];
}

// ---------------------------------------------------------------------------
// FFN (64->128 relu ->64) + residual + LN.  grid 4096 (q rows then k rows), 128 thr
// ---------------------------------------------------------------------------
__global__ __launch_bounds__(128) void ffn_kernel(
    int iblk,
    const float* __restrict__ fw1, const float* __restrict__ fb1,
    const float* __restrict__ fw2, const float* __restrict__ fb2,
    const float* __restrict__ ns, const float* __restrict__ nb)
{
    __shared__ float sx[64], sh[128], so[64], sred[2];
    int row = blockIdx.x, tid = threadIdx.x;
    int side = row >> 11, r = row & 2047;
    const float* src = side ? g_attk : g_attq;
    float* dst = side ? g_kvs : g_qvs;
    if (tid < 64) sx[tid] = src[r*64 + tid];
    __syncthreads();
    const float* W1 = fw1 + iblk*64*128;
    float acc = fb1[iblk*128 + tid];
#pragma unroll 16
    for (int k = 0; k < 64; ++k) acc = fmaf(sx[k], W1[k*128 + tid], acc);
    sh[tid] = fmaxf(acc, 0.f);
    __syncthreads();
    if (tid < 64) {
        const float* W2 = fw2 + iblk*128*64;
        float a2 = fb2[iblk*64 + tid];
#pragma unroll 16
        for (int k = 0; k < 128; ++k) a2 = fmaf(sh[k], W2[k*64 + tid], a2);
        so[tid] = a2 + sx[tid];
    }
    __syncthreads();
    if (tid < 32) {
        float v0 = so[tid], v1 = so[tid + 32];
        float s = v0 + v1;
#pragma unroll
        for (int off = 16; off; off >>= 1)
            s += __shfl_xor_sync(0xffffffffu, s, off);
        float mu = s * (1.f/64.f);
        float e0 = v0 - mu, e1 = v1 - mu;
        float qv = fmaf(e0, e0, e1*e1);
#pragma unroll
        for (int off = 16; off; off >>= 1)
            qv += __shfl_xor_sync(0xffffffffu, qv, off);
        if (tid == 0) { sred[0] = mu; sred[1] = rsqrtf(qv*(1.f/64.f) + 1e-6f); }
    }
    __syncthreads();
    if (tid < 64)
        dst[r*64 + tid] = (so[tid] - sred[0]) * sred[1] * ns[iblk*64 + tid] + nb[iblk*64 + tid];
}

// ---------------------------------------------------------------------------
// Head: final LN + MLP 64->128 relu ->2, split into (mu, std=exp(lv/2))
// grid 2048, 128 thr.  out = [mu(2048) | std(2048)]
// ---------------------------------------------------------------------------
__global__ __launch_bounds__(128) void head_kernel(
    const float* __restrict__ fns, const float* __restrict__ fnb,
    const float* __restrict__ hw1, const float* __restrict__ hb1,
    const float* __restrict__ hw2, const float* __restrict__ hb2,
    float* __restrict__ out)
{
    __shared__ float sx[64], sh[128], sp0[128], sp1[128], sred[2];
    int row = blockIdx.x, tid = threadIdx.x;
    if (tid < 64) sx[tid] = g_qvs[row*64 + tid];
    __syncthreads();
    if (tid < 32) {
        float v0 = sx[tid], v1 = sx[tid + 32];
        float s = v0 + v1;
#pragma unroll
        for (int off = 16; off; off >>= 1)
            s += __shfl_xor_sync(0xffffffffu, s, off);
        float mu = s * (1.f/64.f);
        float e0 = v0 - mu, e1 = v1 - mu;
        float qv = fmaf(e0, e0, e1*e1);
#pragma unroll
        for (int off = 16; off; off >>= 1)
            qv += __shfl_xor_sync(0xffffffffu, qv, off);
        if (tid == 0) { sred[0] = mu; sred[1] = rsqrtf(qv*(1.f/64.f) + 1e-6f); }
    }
    __syncthreads();
    if (tid < 64) sx[tid] = (sx[tid] - sred[0]) * sred[1] * fns[tid] + fnb[tid];
    __syncthreads();
    float acc = hb1[tid];
#pragma unroll 16
    for (int k = 0; k < 64; ++k) acc = fmaf(sx[k], hw1[k*128 + tid], acc);
    sh[tid] = fmaxf(acc, 0.f);
    __syncthreads();
    sp0[tid] = sh[tid] * hw2[tid*2 + 0];
    sp1[tid] = sh[tid] * hw2[tid*2 + 1];
    __syncthreads();
    for (int s = 64; s > 0; s >>= 1) {
        if (tid < s) { sp0[tid] += sp0[tid + s]; sp1[tid] += sp1[tid + s]; }
        __syncthreads();
    }
    if (tid == 0) {
        out[row]        = sp0[0] + hb2[0];
        out[2048 + row] = __expf(0.5f * (sp1[0] + hb2[1]));
    }
}

// ---------------------------------------------------------------------------
extern "C" void kernel_launch(void* const* d_in, const int* in_sizes, int n_in,
                              void* d_out, int out_size)
{
    const float* s_ctx   = (const float*)d_in[0];
    const float* f_ctx   = (const float*)d_in[1];
    const float* s_test  = (const float*)d_in[2];
    const float* table   = (const float*)d_in[3];
    const float* emb_w1  = (const float*)d_in[4];
    const float* emb_b1  = (const float*)d_in[5];
    const float* emb_w2  = (const float*)d_in[6];
    const float* emb_b2  = (const float*)d_in[7];
    const float* attn_wq = (const float*)d_in[8];
    const float* attn_bq = (const float*)d_in[9];
    const float* attn_wk = (const float*)d_in[10];
    const float* attn_bk = (const float*)d_in[11];
    const float* attn_wv = (const float*)d_in[12];
    const float* attn_bv = (const float*)d_in[13];
    const float* attn_wo = (const float*)d_in[14];
    const float* attn_bo = (const float*)d_in[15];
    const float* ffn_w1  = (const float*)d_in[16];
    const float* ffn_b1  = (const float*)d_in[17];
    const float* ffn_w2  = (const float*)d_in[18];
    const float* ffn_b2  = (const float*)d_in[19];
    const float* bias_w1 = (const float*)d_in[20];
    const float* bias_b1 = (const float*)d_in[21];
    const float* bias_w2 = (const float*)d_in[22];
    const float* bias_b2 = (const float*)d_in[23];
    const float* norm_s  = (const float*)d_in[24];
    const float* norm_b  = (const float*)d_in[25];
    const float* fnorm_s = (const float*)d_in[26];
    const float* fnorm_b = (const float*)d_in[27];
    const float* head_w1 = (const float*)d_in[28];
    const float* head_b1 = (const float*)d_in[29];
    const float* head_w2 = (const float*)d_in[30];
    const float* head_b2 = (const float*)d_in[31];

    embed_kernel<<<4096, 256>>>(s_ctx, f_ctx, s_test, table,
                                emb_w1, emb_b1, emb_w2, emb_b2);
    for (int i = 0; i < 6; ++i) {
        proj_kernel<<<dim3(64, 4), 256>>>(i, attn_wq, attn_bq,
                                          attn_wk, attn_bk, attn_wv, attn_bv);
        attn_kernel<<<dim3(128, BB, 2), 256>>>(i, s_test, s_ctx,
                                               bias_w1, bias_b1, bias_w2, bias_b2,
                                               attn_wo, attn_bo, norm_s, norm_b);
        ffn_kernel<<<4096, 128>>>(i, ffn_w1, ffn_b1, ffn_w2, ffn_b2,
                                  norm_s, norm_b);
    }
    head_kernel<<<2048, 128>>>(fnorm_s, fnorm_b, head_w1, head_b1,
                               head_w2, head_b2, (float*)d_out);
}